// round 6
// baseline (speedup 1.0000x reference)
#include <cuda_runtime.h>
#include <cuda_fp16.h>
#include <cuda_bf16.h>

#define DF 128
#define NMAX 50000
#define EMAX 800000
#define NCLS 10

// Scratch (allocation-free __device__ globals).
__device__ __align__(16) __half g_support[(size_t)NMAX * DF];   // fp16 gather source
__device__ __align__(16) float  g_h[(size_t)NMAX * DF];         // fp32 layer activations
__device__ __align__(16) int2   g_edge_s[EMAX];                 // sorted-by-dst (src, bits(w))
__device__ int g_cnt[NMAX + 1];
__device__ int g_rowptr[NMAX + 1];
__device__ int g_cur[NMAX + 1];
__device__ unsigned g_okey[3 * DF];

__device__ __forceinline__ unsigned fenc(float x) {
    unsigned u = __float_as_uint(x);
    return (u & 0x80000000u) ? ~u : (u | 0x80000000u);
}
__device__ __forceinline__ float fdec(unsigned k) {
    unsigned u = (k & 0x80000000u) ? (k & 0x7FFFFFFFu) : ~k;
    return __uint_as_float(u);
}
__device__ __forceinline__ unsigned smem_u32(const void* p) {
    return (unsigned)__cvta_generic_to_shared(p);
}

// ---------------- sort: counting sort of edges by dst -------------------

__global__ __launch_bounds__(256) void init_kernel(int N) {
    int i = blockIdx.x * 256 + threadIdx.x;
    if (i <= N) g_cnt[i] = 0;
    if (i < 3 * DF) g_okey[i] = 0u;
}

__global__ __launch_bounds__(256) void hist_kernel(const int* __restrict__ dst, int E) {
    int e = blockIdx.x * 256 + threadIdx.x;
    if (e < E) atomicAdd(&g_cnt[dst[e]], 1);
}

__global__ __launch_bounds__(1024) void scan_kernel(int N) {
    __shared__ int part[1024];
    __shared__ int carry[1024];
    int t = threadIdx.x;
    int chunk = (N + 1023) / 1024;
    int base = t * chunk;
    int s = 0;
    for (int j = 0; j < chunk; j++) {
        int idx = base + j;
        if (idx < N) s += g_cnt[idx];
    }
    part[t] = s;
    __syncthreads();
    for (int off = 1; off < 1024; off <<= 1) {
        int v = part[t];
        int add = (t >= off) ? part[t - off] : 0;
        __syncthreads();
        part[t] = v + add;
        __syncthreads();
    }
    carry[t] = (t == 0) ? 0 : part[t - 1];
    __syncthreads();
    int run = carry[t];
    for (int j = 0; j < chunk; j++) {
        int idx = base + j;
        if (idx < N) {
            g_rowptr[idx] = run;
            g_cur[idx] = run;
            run += g_cnt[idx];
        }
    }
    if (base < N && base + chunk >= N) g_rowptr[N] = run;
}

__global__ __launch_bounds__(256) void reorder_kernel(const int* __restrict__ src,
                                                      const int* __restrict__ dst,
                                                      const float* __restrict__ w,
                                                      int E) {
    int e = blockIdx.x * 256 + threadIdx.x;
    if (e >= E) return;
    int d = dst[e];
    int pos = atomicAdd(&g_cur[d], 1);
    g_edge_s[pos] = make_int2(src[e], __float_as_int(w[e]));
}

// ---------------- GEMM: support(fp16) = Ain(fp32) @ W, fp16 m16n8k16 mma ---
// Block tile 128x128, 8 warps 4(m)x2(n); warp tile 32x64 = 2(m)x8(n) mma
// tiles, K=128 in 8 k-steps of 16. Fragments via ldmatrix (conflict-free,
// row stride 136 halves = 272B). fp16 mantissa == tf32 mantissa; fp32 accum.

#define SH 136   // half-element stride of both smem tiles
#define GEMM_SMEM (2 * DF * SH * (int)sizeof(__half))  // 69632 B

__global__ __launch_bounds__(256, 2) void gemm_kernel(const float* __restrict__ A,
                                                      const float* __restrict__ W,
                                                      int N, int use_gh) {
    extern __shared__ __half smem_h[];
    __half* Ws = smem_h;             // [128 k][136 n]
    __half* As = smem_h + DF * SH;   // [128 m][136 k]
    const float* Ain = use_gh ? g_h : A;

    int t = threadIdx.x;
    int lane = t & 31;
    int wrp = t >> 5;
    int wm = wrp >> 1;   // 0..3
    int wn = wrp & 1;    // 0..1
    int r0 = blockIdx.x * 128;

    // Stage W [k][n] fp32 -> fp16 (contiguous n writes).
    for (int i = t; i < DF * 32; i += 256) {
        int k = i >> 5;
        int n4 = (i & 31) * 4;
        float4 wv = *(const float4*)&W[k * DF + n4];
        __half2* dstp = (__half2*)&Ws[k * SH + n4];
        dstp[0] = __floats2half2_rn(wv.x, wv.y);
        dstp[1] = __floats2half2_rn(wv.z, wv.w);
    }
    // Stage A [m][k] fp32 -> fp16 (full 128x128 tile, single stage).
    for (int i = t; i < DF * 32; i += 256) {
        int row = i >> 5;
        int k4 = (i & 31) * 4;
        int gr = r0 + row;
        float4 av = make_float4(0.f, 0.f, 0.f, 0.f);
        if (gr < N) av = *(const float4*)&Ain[(size_t)gr * DF + k4];
        __half2* dstp = (__half2*)&As[row * SH + k4];
        dstp[0] = __floats2half2_rn(av.x, av.y);
        dstp[1] = __floats2half2_rn(av.z, av.w);
    }
    __syncthreads();

    float acc[2][8][4];
#pragma unroll
    for (int mt = 0; mt < 2; mt++)
#pragma unroll
        for (int nt = 0; nt < 8; nt++)
#pragma unroll
            for (int r = 0; r < 4; r++) acc[mt][nt][r] = 0.f;

    int gid = lane >> 2;
    int tig = lane & 3;

    // ldmatrix lane-address bases (kb = 0); advance per k-step.
    int tr = lane & 7;
    int tile = lane >> 3;
    int row_off = (tile & 1) ? 8 : 0;
    int col_off = (tile & 2) ? 8 : 0;
    // A tiles: rows m0+tr(+8), cols kb(+8)
    unsigned addrA[2];
#pragma unroll
    for (int mt = 0; mt < 2; mt++) {
        int m0 = wm * 32 + mt * 16;
        addrA[mt] = smem_u32(&As[(m0 + tr + row_off) * SH + col_off]);
    }
    // B tiles (trans): rows kb+tr(+8), cols nb(+8); np covers n-pair (2 mma n-tiles)
    unsigned addrB[4];
#pragma unroll
    for (int np = 0; np < 4; np++) {
        int nb = wn * 64 + np * 16;
        addrB[np] = smem_u32(&Ws[(tr + row_off) * SH + nb + col_off]);
    }

#pragma unroll
    for (int ks = 0; ks < 8; ks++) {
        unsigned af[2][4];
#pragma unroll
        for (int mt = 0; mt < 2; mt++) {
            asm volatile(
                "ldmatrix.sync.aligned.m8n8.x4.shared.b16 {%0,%1,%2,%3}, [%4];"
                : "=r"(af[mt][0]), "=r"(af[mt][1]), "=r"(af[mt][2]), "=r"(af[mt][3])
                : "r"(addrA[mt] + ks * 16 * (unsigned)sizeof(__half)));
        }
        unsigned bf[4][4];
#pragma unroll
        for (int np = 0; np < 4; np++) {
            asm volatile(
                "ldmatrix.sync.aligned.m8n8.x4.trans.shared.b16 {%0,%1,%2,%3}, [%4];"
                : "=r"(bf[np][0]), "=r"(bf[np][1]), "=r"(bf[np][2]), "=r"(bf[np][3])
                : "r"(addrB[np] + ks * 16 * SH * (unsigned)sizeof(__half)));
        }
#pragma unroll
        for (int np = 0; np < 4; np++) {
#pragma unroll
            for (int sub = 0; sub < 2; sub++) {
                int nt = np * 2 + sub;
#pragma unroll
                for (int mt = 0; mt < 2; mt++) {
                    asm volatile(
                        "mma.sync.aligned.m16n8k16.row.col.f32.f16.f16.f32 "
                        "{%0,%1,%2,%3}, {%4,%5,%6,%7}, {%8,%9}, {%0,%1,%2,%3};"
                        : "+f"(acc[mt][nt][0]), "+f"(acc[mt][nt][1]),
                          "+f"(acc[mt][nt][2]), "+f"(acc[mt][nt][3])
                        : "r"(af[mt][0]), "r"(af[mt][1]),
                          "r"(af[mt][2]), "r"(af[mt][3]),
                        "r"(bf[np][sub * 2]), "r"(bf[np][sub * 2 + 1]));
                }
            }
        }
    }

#pragma unroll
    for (int mt = 0; mt < 2; mt++) {
#pragma unroll
        for (int nt = 0; nt < 8; nt++) {
            int row = r0 + wm * 32 + mt * 16 + gid;
            int col = wn * 64 + nt * 8 + 2 * tig;
            if (row < N)
                *(__half2*)&g_support[(size_t)row * DF + col] =
                    __floats2half2_rn(acc[mt][nt][0], acc[mt][nt][1]);
            if (row + 8 < N)
                *(__half2*)&g_support[(size_t)(row + 8) * DF + col] =
                    __floats2half2_rn(acc[mt][nt][2], acc[mt][nt][3]);
        }
    }
}

// ---------------- segment-sum + bias (+relu, h write) + column max --------
// (unchanged from R5)

__device__ __forceinline__ void edge_fma(float4& a, const uint2 u, const float w) {
    float2 lo = __half22float2(*(const __half2*)&u.x);
    float2 hi = __half22float2(*(const __half2*)&u.y);
    a.x += lo.x * w; a.y += lo.y * w;
    a.z += hi.x * w; a.w += hi.y * w;
}

__global__ __launch_bounds__(256) void seg_kernel(const float* __restrict__ b,
                                                  int N, int layer, int do_relu) {
    __shared__ unsigned smax[DF];
    int t = threadIdx.x;
    int lane = t & 31;
    int wrp = t >> 5;
    if (t < DF) smax[t] = 0u;
    __syncthreads();

    int d = blockIdx.x * 8 + wrp;
    if (d < N) {
        int beg = g_rowptr[d];
        int end = g_rowptr[d + 1];
        const uint2* sup = (const uint2*)g_support;

        float4 acc0 = make_float4(0.f, 0.f, 0.f, 0.f);
        float4 acc1 = make_float4(0.f, 0.f, 0.f, 0.f);

        for (int base = beg; base < end; base += 32) {
            int m = end - base;
            if (m > 32) m = 32;
            int2 dsc = make_int2(0, 0);
            if (lane < m) dsc = g_edge_s[base + lane];

            int j = 0;
            for (; j + 8 <= m; j += 8) {
                int s0 = __shfl_sync(0xffffffffu, dsc.x, j + 0);
                int s1 = __shfl_sync(0xffffffffu, dsc.x, j + 1);
                int s2 = __shfl_sync(0xffffffffu, dsc.x, j + 2);
                int s3 = __shfl_sync(0xffffffffu, dsc.x, j + 3);
                int s4 = __shfl_sync(0xffffffffu, dsc.x, j + 4);
                int s5 = __shfl_sync(0xffffffffu, dsc.x, j + 5);
                int s6 = __shfl_sync(0xffffffffu, dsc.x, j + 6);
                int s7 = __shfl_sync(0xffffffffu, dsc.x, j + 7);
                float w0 = __int_as_float(__shfl_sync(0xffffffffu, dsc.y, j + 0));
                float w1 = __int_as_float(__shfl_sync(0xffffffffu, dsc.y, j + 1));
                float w2 = __int_as_float(__shfl_sync(0xffffffffu, dsc.y, j + 2));
                float w3 = __int_as_float(__shfl_sync(0xffffffffu, dsc.y, j + 3));
                float w4 = __int_as_float(__shfl_sync(0xffffffffu, dsc.y, j + 4));
                float w5 = __int_as_float(__shfl_sync(0xffffffffu, dsc.y, j + 5));
                float w6 = __int_as_float(__shfl_sync(0xffffffffu, dsc.y, j + 6));
                float w7 = __int_as_float(__shfl_sync(0xffffffffu, dsc.y, j + 7));
                uint2 u0 = sup[(size_t)s0 * 32 + lane];
                uint2 u1 = sup[(size_t)s1 * 32 + lane];
                uint2 u2 = sup[(size_t)s2 * 32 + lane];
                uint2 u3 = sup[(size_t)s3 * 32 + lane];
                uint2 u4 = sup[(size_t)s4 * 32 + lane];
                uint2 u5 = sup[(size_t)s5 * 32 + lane];
                uint2 u6 = sup[(size_t)s6 * 32 + lane];
                uint2 u7 = sup[(size_t)s7 * 32 + lane];
                edge_fma(acc0, u0, w0);
                edge_fma(acc1, u1, w1);
                edge_fma(acc0, u2, w2);
                edge_fma(acc1, u3, w3);
                edge_fma(acc0, u4, w4);
                edge_fma(acc1, u5, w5);
                edge_fma(acc0, u6, w6);
                edge_fma(acc1, u7, w7);
            }
            for (; j + 2 <= m; j += 2) {
                int s0 = __shfl_sync(0xffffffffu, dsc.x, j + 0);
                int s1 = __shfl_sync(0xffffffffu, dsc.x, j + 1);
                float w0 = __int_as_float(__shfl_sync(0xffffffffu, dsc.y, j + 0));
                float w1 = __int_as_float(__shfl_sync(0xffffffffu, dsc.y, j + 1));
                uint2 u0 = sup[(size_t)s0 * 32 + lane];
                uint2 u1 = sup[(size_t)s1 * 32 + lane];
                edge_fma(acc0, u0, w0);
                edge_fma(acc1, u1, w1);
            }
            if (j < m) {
                int s0 = __shfl_sync(0xffffffffu, dsc.x, j);
                float w0 = __int_as_float(__shfl_sync(0xffffffffu, dsc.y, j));
                uint2 u0 = sup[(size_t)s0 * 32 + lane];
                edge_fma(acc0, u0, w0);
            }
        }

        float4 v;
        const float4* bb = (const float4*)b;
        float4 bv = bb[lane];
        v.x = acc0.x + acc1.x + bv.x;
        v.y = acc0.y + acc1.y + bv.y;
        v.z = acc0.z + acc1.z + bv.z;
        v.w = acc0.w + acc1.w + bv.w;
        if (do_relu) {
            v.x = fmaxf(v.x, 0.f); v.y = fmaxf(v.y, 0.f);
            v.z = fmaxf(v.z, 0.f); v.w = fmaxf(v.w, 0.f);
            *(float4*)&g_h[(size_t)d * DF + lane * 4] = v;
        }
        atomicMax(&smax[lane * 4 + 0], fenc(v.x));
        atomicMax(&smax[lane * 4 + 1], fenc(v.y));
        atomicMax(&smax[lane * 4 + 2], fenc(v.z));
        atomicMax(&smax[lane * 4 + 3], fenc(v.w));
    }
    __syncthreads();
    if (t < DF) atomicMax(&g_okey[layer * DF + t], smax[t]);
}

// ---------------- head ----------------------------------------------------

__global__ __launch_bounds__(128) void final_kernel(const float* __restrict__ lin_W,
                                                    const float* __restrict__ lin_b,
                                                    float* __restrict__ out) {
    __shared__ float lin_in[3 * DF];
    __shared__ float logits[NCLS];
    int t = threadIdx.x;
    for (int i = t; i < 3 * DF; i += 128) lin_in[i] = fdec(g_okey[i]);
    __syncthreads();
    if (t < NCLS) {
        float s = lin_b[t];
#pragma unroll 4
        for (int j = 0; j < 3 * DF; j++) s += lin_W[t * 3 * DF + j] * lin_in[j];
        logits[t] = s;
    }
    __syncthreads();
    if (t == 0) {
        float m = -3.402823466e+38f;
        for (int c = 0; c < NCLS; c++) m = fmaxf(m, logits[c]);
        float se = 0.f;
        for (int c = 0; c < NCLS; c++) se += expf(logits[c] - m);
        float lse = m + logf(se);
        for (int c = 0; c < NCLS; c++) out[c] = logits[c] - lse;
    }
}

extern "C" void kernel_launch(void* const* d_in, const int* in_sizes, int n_in,
                              void* d_out, int out_size) {
    const float* x    = (const float*)d_in[0];
    const int*   esrc = (const int*)d_in[1];
    const int*   edst = (const int*)d_in[2];
    const float* ew   = (const float*)d_in[3];
    const float* W1   = (const float*)d_in[4];
    const float* b1   = (const float*)d_in[5];
    const float* W2   = (const float*)d_in[6];
    const float* b2   = (const float*)d_in[7];
    const float* W3   = (const float*)d_in[8];
    const float* b3   = (const float*)d_in[9];
    const float* linW = (const float*)d_in[10];
    const float* linb = (const float*)d_in[11];
    float* out = (float*)d_out;

    int N = in_sizes[0] / DF;
    int E = in_sizes[1];

    static int attr_set = 0;
    if (!attr_set) {
        cudaFuncSetAttribute(gemm_kernel, cudaFuncAttributeMaxDynamicSharedMemorySize, GEMM_SMEM);
        attr_set = 1;
    }

    int eb = (E + 255) / 256;
    int gemm_blocks = (N + 127) / 128;
    int seg_blocks = (N + 7) / 8;

    init_kernel<<<(N + 256) / 256, 256>>>(N);
    hist_kernel<<<eb, 256>>>(edst, E);
    scan_kernel<<<1, 1024>>>(N);
    reorder_kernel<<<eb, 256>>>(esrc, edst, ew, E);

    gemm_kernel<<<gemm_blocks, 256, GEMM_SMEM>>>(x, W1, N, 0);
    seg_kernel<<<seg_blocks, 256>>>(b1, N, 0, 1);
    gemm_kernel<<<gemm_blocks, 256, GEMM_SMEM>>>(nullptr, W2, N, 1);
    seg_kernel<<<seg_blocks, 256>>>(b2, N, 1, 1);
    gemm_kernel<<<gemm_blocks, 256, GEMM_SMEM>>>(nullptr, W3, N, 2);
    seg_kernel<<<seg_blocks, 256>>>(b3, N, 2, 0);
    final_kernel<<<1, 128>>>(linW, linb, out);
}